// round 5
// baseline (speedup 1.0000x reference)
#include <cuda_runtime.h>
#include <math.h>

#define BB 64
#define TT 512
#define II 256
#define OO 1024
#define MM 8
#define IMM 2048
#define NBLK 148
#define NT 512
#define KSR 12                 // REC k-splits per tile
#define KSA 8                  // ACT k-splits per tile
#define NRECT 8                // REC tiles of 256 cols
#define NACTT 4                // ACT tiles of 256 cols
#define NREC (NRECT * KSR)     // 96
#define NACT (NACTT * KSA)     // 32
#define NGEMM (NREC + NACT)    // 128
#define NGATE 16
#define GATE0 NGEMM            // 128..143
#define RELEASER 147
#define DYN_SMEM (16*64*4 + 16*256*4)   // 20480 B

// ---------------- persistent device state ------------------------------------
__device__ float g_H[2][BB * OO];          // h carry (double buffered)
__device__ float g_XP[2][BB * IMM];        // x_pred carry (double buffered)
__device__ float g_Pact[KSA][BB * OO];     // split-K partials (acts)
__device__ float g_Prec[KSR][BB * IMM];    // split-K partials (acts_rec)
__device__ float g_lse[IMM];
__device__ float g_gate[BB * MM];
__device__ volatile unsigned g_parr[NRECT + NACTT][16];  // per-tile arrival flags
__device__ volatile unsigned g_gdone[NGATE];             // gate finished flags
__device__ volatile unsigned g_garr[NGATE];              // gate mini-barrier
__device__ volatile unsigned g_ggen;
__device__ volatile unsigned g_arr[NBLK];                // grid arrival flags
__device__ volatile unsigned g_gen;                      // grid release gen

// ---------------- grid barrier helpers (monotonic, replay-safe) --------------
__device__ __forceinline__ void grid_arrive(unsigned tgt) {
    __syncthreads();
    if (threadIdx.x == 0) { __threadfence(); g_arr[blockIdx.x] = tgt; }
}
__device__ __forceinline__ void grid_wait(unsigned tgt) {
    const int tid = threadIdx.x;
    if (blockIdx.x == RELEASER) {
        if (tid < NBLK) { while ((int)(g_arr[tid] - tgt) < 0) {} }
        __syncthreads();
        if (tid == 0) { __threadfence(); g_gen = tgt; }
    } else {
        if (tid == 0) {
            while ((int)(g_gen - tgt) < 0) { __nanosleep(32); }
            __threadfence();
        }
    }
    __syncthreads();
}

// ---------------- packed f32x2 helpers ---------------------------------------
__device__ __forceinline__ unsigned long long splat2(float v) {
    unsigned long long r;
    asm("mov.b64 %0, {%1, %1};" : "=l"(r) : "f"(v));
    return r;
}
__device__ __forceinline__ void ffma2(unsigned long long& d, unsigned long long a,
                                      unsigned long long b) {
    asm("fma.rn.f32x2 %0, %1, %2, %0;" : "+l"(d) : "l"(a), "l"(b));
}
__device__ __forceinline__ float2 unpack2(unsigned long long v) {
    float2 r;
    asm("mov.b64 {%0, %1}, %2;" : "=f"(r.x), "=f"(r.y) : "l"(v));
    return r;
}

// ---------------- 64x256-tile GEMM chunk, software-pipelined k loop ----------
__device__ __forceinline__ void gemm_unit(
    const float* xb, int xs, const float* cb, int cs,
    const float* __restrict__ W1, int ld1,
    const float* __restrict__ W2, int ld2,
    int col0, int k0, int nsub,
    float* __restrict__ P, int NC, float* dynsh)
{
    float* sA = dynsh;              // [16][64]  k-major
    float* sB = dynsh + 16 * 64;    // [16][256] k-major
    const int tid = threadIdx.x;
    const int wid = tid >> 5, lane = tid & 31;
    const int bg = wid >> 1;                 // batch group (8 batches)
    const int cg = (wid & 1) * 32 + lane;    // col group (4 cols)
    const int jc = tid & 255;                // sB loader col
    const int kh = (tid >> 8) * 8;           // sB loader k-offset
    const int row = tid & 63;                // sA loader row (tid<256)
    const int kq = ((tid >> 6) & 3) * 4;     // sA loader k-offset

    unsigned long long acc[4][4];
#pragma unroll
    for (int c = 0; c < 4; c++)
#pragma unroll
        for (int p = 0; p < 4; p++) acc[c][p] = 0ull;

    const int j = col0 + jc;
    float wbuf[8]; float4 abuf;
    {
        const int kb = k0;
        const float* ws = ((kb < II) ? (W1 + (size_t)j * ld1 + kb)
                                     : (W2 + (size_t)j * ld2 + (kb - II))) + kh;
        *(float4*)&wbuf[0] = __ldg((const float4*)ws);
        *(float4*)&wbuf[4] = __ldg((const float4*)(ws + 4));
        if (tid < 256) {
            const float* as = (kb < II) ? (xb + row * xs + kb + kq)
                                        : (cb + row * cs + (kb - II) + kq);
            abuf = __ldcg((const float4*)as);
        }
    }

    for (int s = 0; s < nsub; s++) {
#pragma unroll
        for (int i = 0; i < 8; i++) sB[(kh + i) * 256 + jc] = wbuf[i];
        if (tid < 256) {
            sA[(kq + 0) * 64 + row] = abuf.x;
            sA[(kq + 1) * 64 + row] = abuf.y;
            sA[(kq + 2) * 64 + row] = abuf.z;
            sA[(kq + 3) * 64 + row] = abuf.w;
        }
        __syncthreads();

        if (s + 1 < nsub) {
            const int kb = k0 + (s + 1) * 16;
            const float* ws = ((kb < II) ? (W1 + (size_t)j * ld1 + kb)
                                         : (W2 + (size_t)j * ld2 + (kb - II))) + kh;
            *(float4*)&wbuf[0] = __ldg((const float4*)ws);
            *(float4*)&wbuf[4] = __ldg((const float4*)(ws + 4));
            if (tid < 256) {
                const float* as = (kb < II) ? (xb + row * xs + kb + kq)
                                            : (cb + row * cs + (kb - II) + kq);
                abuf = __ldcg((const float4*)as);
            }
        }

        // software-pipelined k loop: load k+1 operands while computing k
        ulonglong2 a01 = *(const ulonglong2*)(sA + bg * 8);
        ulonglong2 a23 = *(const ulonglong2*)(sA + bg * 8 + 4);
        float4 wv = *(const float4*)(sB + cg * 4);
#pragma unroll
        for (int k = 0; k < 16; k++) {
            ulonglong2 na01 = a01, na23 = a23; float4 nwv = wv;
            if (k < 15) {
                const float* pa = sA + (k + 1) * 64 + bg * 8;
                na01 = *(const ulonglong2*)pa;
                na23 = *(const ulonglong2*)(pa + 4);
                nwv  = *(const float4*)(sB + (k + 1) * 256 + cg * 4);
            }
            unsigned long long w0 = splat2(wv.x), w1 = splat2(wv.y);
            unsigned long long w2 = splat2(wv.z), w3 = splat2(wv.w);
            ffma2(acc[0][0], a01.x, w0); ffma2(acc[0][1], a01.y, w0);
            ffma2(acc[0][2], a23.x, w0); ffma2(acc[0][3], a23.y, w0);
            ffma2(acc[1][0], a01.x, w1); ffma2(acc[1][1], a01.y, w1);
            ffma2(acc[1][2], a23.x, w1); ffma2(acc[1][3], a23.y, w1);
            ffma2(acc[2][0], a01.x, w2); ffma2(acc[2][1], a01.y, w2);
            ffma2(acc[2][2], a23.x, w2); ffma2(acc[2][3], a23.y, w2);
            ffma2(acc[3][0], a01.x, w3); ffma2(acc[3][1], a01.y, w3);
            ffma2(acc[3][2], a23.x, w3); ffma2(acc[3][3], a23.y, w3);
            a01 = na01; a23 = na23; wv = nwv;
        }
        __syncthreads();
    }

#pragma unroll
    for (int p = 0; p < 4; p++) {
        float2 v0 = unpack2(acc[0][p]), v1 = unpack2(acc[1][p]);
        float2 v2 = unpack2(acc[2][p]), v3 = unpack2(acc[3][p]);
        const int b0 = bg * 8 + 2 * p;
        float* d0 = P + (size_t)b0 * NC + col0 + cg * 4;
        float* d1 = d0 + NC;
        *(float4*)d0 = make_float4(v0.x, v1.x, v2.x, v3.x);
        *(float4*)d1 = make_float4(v0.y, v1.y, v2.y, v3.y);
    }
}

// ---------------- gate work (16 CTAs), overlapped with GEMM phase -------------
__device__ __forceinline__ void gate_work(
    int t, const float* __restrict__ XPold, const float* __restrict__ x,
    const float* __restrict__ periods, const float* __restrict__ shifts,
    float* __restrict__ out_ps, unsigned tgt)
{
    const int gi = blockIdx.x - GATE0;       // 0..15
    const int tid = threadIdx.x, wid = tid >> 5, lane = tid & 31;

    // pass 1: batch-axis logsumexp for 128 cols
#pragma unroll
    for (int it = 0; it < 8; it++) {
        const int col = gi * 128 + it * 16 + wid;
        float v0 = __ldcg(&XPold[lane * IMM + col]);
        float v1 = __ldcg(&XPold[(lane + 32) * IMM + col]);
        float m = fmaxf(v0, v1);
#pragma unroll
        for (int off = 16; off > 0; off >>= 1)
            m = fmaxf(m, __shfl_xor_sync(0xffffffffu, m, off));
        float s = expf(v0 - m) + expf(v1 - m);
#pragma unroll
        for (int off = 16; off > 0; off >>= 1)
            s += __shfl_xor_sync(0xffffffffu, s, off);
        if (lane == 0) g_lse[col] = m + logf(s);
    }
    // mini-barrier among the 16 gate CTAs
    __syncthreads();
    if (tid == 0) { __threadfence(); g_garr[gi] = tgt; }
    if (gi == 0) {
        if (tid < NGATE) { while ((int)(g_garr[tid] - tgt) < 0) {} }
        __syncthreads();
        if (tid == 0) { __threadfence(); g_ggen = tgt; }
        __syncthreads();
    } else {
        if (tid == 0) { while ((int)(g_ggen - tgt) < 0) {} __threadfence(); }
        __syncthreads();
    }
    // pass 2: surprisal -> mp -> gate, 2 (b,m) pairs per warp
#pragma unroll
    for (int uu = 0; uu < 2; uu++) {
        const int u = gi * 32 + wid * 2 + uu;
        const int b = u >> 3, mo = u & 7;
        float s = 0.f;
#pragma unroll
        for (int i0 = 0; i0 < II; i0 += 32) {
            const int i = i0 + lane;
            s += (__ldcg(&XPold[b * IMM + mo * II + i]) - __ldcg(&g_lse[mo * II + i]))
                 * __ldg(&x[((size_t)b * TT + t) * II + i]);
        }
#pragma unroll
        for (int off = 16; off > 0; off >>= 1)
            s += __shfl_xor_sync(0xffffffffu, s, off);
        if (lane == 0) {
            const float mp = s * (1.f / (float)II) * __ldg(&periods[mo]);
            out_ps[((size_t)b * TT + t) * MM + mo] = mp;
            g_gate[u] = (sinf((float)t * mp + __ldg(&shifts[mo])) + 1.f) * 0.5f;
        }
    }
    __syncthreads();
    if (tid == 0) { __threadfence(); g_gdone[gi] = tgt; }
}

// ---------------- persistent kernel ------------------------------------------
__global__ void __launch_bounds__(NT, 1)
cwrnn_kernel(const float* __restrict__ x, const float* __restrict__ W_in,
             const float* __restrict__ b_in, const float* __restrict__ W_h,
             const float* __restrict__ W_ir, const float* __restrict__ b_ir,
             const float* __restrict__ W_hr, const float* __restrict__ periods,
             const float* __restrict__ shifts, float* __restrict__ out)
{
    extern __shared__ float dynsh[];
    const int bid = blockIdx.x, tid = threadIdx.x;
    const int gstep = NBLK * NT;
    float* out_ys = out;
    float* out_hf = out + (size_t)BB * TT * OO;
    float* out_ps = out_hf + BB * OO;

    const unsigned base = g_gen;   // monotonic across graph replays

    for (int idx = bid * NT + tid; idx < BB * OO; idx += gstep) g_H[0][idx] = 0.f;
    for (int idx = bid * NT + tid; idx < BB * IMM; idx += gstep) g_XP[0][idx] = 0.f;
    grid_arrive(base + 1);
    grid_wait(base + 1);

    for (int t = 0; t < TT; t++) {
        const unsigned tgt = base + 2 + t;
        const int p = t & 1;
        const float* xb = x + (size_t)t * II;

        if (bid < NREC) {
            // ===== REC GEMM + fused in-tile reduction ========================
            const int tile = bid / KSR, ks = bid - tile * KSR;
            gemm_unit(xb, TT * II, g_XP[p], IMM, W_ir, II, W_hr, IMM,
                      tile * 256, ks * 192, 12, g_Prec[ks], IMM, dynsh);
            __syncthreads();
            if (tid == 0) { __threadfence(); g_parr[tile][ks] = tgt; }
            if (tid < KSR) { while ((int)(g_parr[tile][tid] - tgt) < 0) {} }
            __syncthreads();
            const int w  = (ks < 8) ? 22 : 20;
            const int s0 = (ks < 8) ? 22 * ks : 176 + 20 * (ks - 8);
            const int cbase = tile * 256 + s0;
            for (int i = tid; i < BB * w; i += NT) {
                const int b = i / w, jj = cbase + (i - b * w);
                float s = __ldg(&b_ir[jj]);
#pragma unroll
                for (int k2 = 0; k2 < KSR; k2++)
                    s += __ldcg(&g_Prec[k2][b * IMM + jj]);
                g_XP[p ^ 1][b * IMM + jj] = tanhf(s);
            }
            grid_arrive(tgt);
        } else if (bid < NGEMM) {
            // ===== ACT GEMM + fused reduction + gate blend + outputs =========
            const int v = bid - NREC, tile = v / KSA, ks = v - tile * KSA;
            gemm_unit(xb, TT * II, g_H[p], OO, W_in, II, W_h, OO,
                      tile * 256, ks * 160, 10, g_Pact[ks], OO, dynsh);
            __syncthreads();
            if (tid == 0) { __threadfence(); g_parr[NRECT + tile][ks] = tgt; }
            if (tid < KSA) { while ((int)(g_parr[NRECT + tile][tid] - tgt) < 0) {} }
            if (tid < NGATE) {
                while ((int)(g_gdone[tid] - tgt) < 0) { __nanosleep(32); }
            }
            __syncthreads();
            const int cbase = tile * 256 + ks * 32;
#pragma unroll
            for (int it = 0; it < 4; it++) {
                const int i = it * NT + tid;
                const int b = i >> 5, o = cbase + (i & 31);
                float s = __ldg(&b_in[o]);
#pragma unroll
                for (int k2 = 0; k2 < KSA; k2++)
                    s += __ldcg(&g_Pact[k2][b * OO + o]);
                const float a = tanhf(s);
                const float g = __ldcg(&g_gate[b * MM + (o >> 7)]);
                const float h = __ldcg(&g_H[p][b * OO + o]);
                const float y = (1.f - g) * a + g * h;
                out_ys[((size_t)b * TT + t) * OO + o] = y;
                g_H[p ^ 1][b * OO + o] = y;
                if (t == TT - 1) out_hf[b * OO + o] = y;
            }
            grid_arrive(tgt);
        } else if (bid < GATE0 + NGATE) {
            gate_work(t, g_XP[p], x, periods, shifts, out_ps, tgt);
            grid_arrive(tgt);
        } else {
            grid_arrive(tgt);   // spares (incl. releaser)
        }
        grid_wait(tgt);
    }
}

extern "C" void kernel_launch(void* const* d_in, const int* in_sizes, int n_in,
                              void* d_out, int out_size) {
    (void)in_sizes; (void)n_in; (void)out_size;
    const float* x       = (const float*)d_in[0];
    const float* W_in    = (const float*)d_in[1];
    const float* b_in    = (const float*)d_in[2];
    const float* W_h     = (const float*)d_in[3];
    const float* W_ir    = (const float*)d_in[4];
    const float* b_ir    = (const float*)d_in[5];
    const float* W_hr    = (const float*)d_in[6];
    const float* periods = (const float*)d_in[7];
    const float* shifts  = (const float*)d_in[8];
    float* out = (float*)d_out;

    cwrnn_kernel<<<NBLK, NT, DYN_SMEM>>>(x, W_in, b_in, W_h, W_ir, b_ir, W_hr,
                                         periods, shifts, out);
}